// round 3
// baseline (speedup 1.0000x reference)
#include <cuda_runtime.h>

#define FULLMASK 0xffffffffu
#define WSTRIDE 258

// ---- smem layout (float offsets) ----
#define OFF_W1T  0                      // [64][258]  Whh1^T
#define OFF_W2T  (64 * WSTRIDE)         // [128][258] rows 0..63 Wih2^T, 64..127 Whh2^T
#define OFF_WIH1 (OFF_W2T + 128 * WSTRIDE)
#define OFF_CB1  (OFF_WIH1 + 256)
#define OFF_CB2  (OFF_CB1 + 256)
#define OFF_WOUT (OFF_CB2 + 256)        // [2][1664]
#define OFF_XS   (OFF_WOUT + 3328)      // [64][24]
#define SMEM_FLOATS (OFF_XS + 64 * 24)
#define SMEM_BYTES  (SMEM_FLOATS * 4)   // 220672 B

static __device__ __forceinline__ unsigned long long splat2(float x) {
    unsigned long long d;
    asm("mov.b64 %0, {%1, %1};" : "=l"(d) : "f"(x));
    return d;
}
static __device__ __forceinline__ float2 unpack2(unsigned long long v) {
    float lo, hi;
    asm("mov.b64 {%0, %1}, %2;" : "=f"(lo), "=f"(hi) : "l"(v));
    return make_float2(lo, hi);
}
static __device__ __forceinline__ unsigned long long fma2(unsigned long long a,
                                                          unsigned long long b,
                                                          unsigned long long c) {
    unsigned long long d;
    asm("fma.rn.f32x2 %0, %1, %2, %3;" : "=l"(d) : "l"(a), "l"(b), "l"(c));
    return d;
}
static __device__ __forceinline__ float sigf(float x) {
    return __fdividef(1.0f, 1.0f + __expf(-x));
}
static __device__ __forceinline__ float tanhf_fast(float x) {
    return 2.0f * __fdividef(1.0f, 1.0f + __expf(-2.0f * x)) - 1.0f;
}

// 64-row matvec accumulation: acc[g][j] (f32x2 over neuron pair n0,n0+1) +=
// src[h] * W[h][g*64 + n0..n0+1], src broadcast from owning lane via shfl.
static __device__ __forceinline__ void gemm64(unsigned long long (&acc)[4][8],
                                              const float* __restrict__ wbase,
                                              const float (&src)[2][8], int n0) {
#pragma unroll 2
    for (int h2 = 0; h2 < 32; ++h2) {
        const float* wr = wbase + (h2 * 2) * WSTRIDE;
        unsigned long long w2a[4], w2b[4];
#pragma unroll
        for (int g = 0; g < 4; ++g) {
            w2a[g] = *(const unsigned long long*)(wr + g * 64 + n0);
            w2b[g] = *(const unsigned long long*)(wr + WSTRIDE + g * 64 + n0);
        }
#pragma unroll
        for (int j = 0; j < 8; ++j) {
            unsigned long long sa = splat2(__shfl_sync(FULLMASK, src[0][j], h2));
#pragma unroll
            for (int g = 0; g < 4; ++g) acc[g][j] = fma2(sa, w2a[g], acc[g][j]);
        }
#pragma unroll
        for (int j = 0; j < 8; ++j) {
            unsigned long long sb = splat2(__shfl_sync(FULLMASK, src[1][j], h2));
#pragma unroll
            for (int g = 0; g < 4; ++g) acc[g][j] = fma2(sb, w2b[g], acc[g][j]);
        }
    }
}

__global__ void __launch_bounds__(256, 1)
snn_kernel(const float* __restrict__ x,
           const float* __restrict__ Wih1, const float* __restrict__ Whh1,
           const float* __restrict__ bih1, const float* __restrict__ bhh1,
           const float* __restrict__ thr1p,
           const float* __restrict__ Wih2, const float* __restrict__ Whh2,
           const float* __restrict__ bih2, const float* __restrict__ bhh2,
           const float* __restrict__ thr2p,
           const float* __restrict__ Wout, const float* __restrict__ bout,
           float* __restrict__ out) {
    extern __shared__ float sm[];
    const int tid  = threadIdx.x;
    const int lane = tid & 31;
    const int w    = tid >> 5;
    const int n0   = lane << 1;          // this lane's neuron pair
    const int bl   = w << 3;             // local batch base (8 per warp)
    const int cta_b0 = blockIdx.x * 64;

    // ---- stage weights (transposed, stride 258 -> conflict-free reads) ----
    for (int i = tid; i < 256 * 64; i += 256) {
        int r = i >> 6, h = i & 63;
        sm[OFF_W1T + h * WSTRIDE + r]        = Whh1[i];
        sm[OFF_W2T + h * WSTRIDE + r]        = Wih2[i];
        sm[OFF_W2T + (64 + h) * WSTRIDE + r] = Whh2[i];
    }
    if (tid < 256) {
        sm[OFF_WIH1 + tid] = Wih1[tid];
        sm[OFF_CB1 + tid]  = bih1[tid] + bhh1[tid];
        sm[OFF_CB2 + tid]  = bih2[tid] + bhh2[tid];
    }
    for (int i = tid; i < 3328; i += 256) sm[OFF_WOUT + i] = Wout[i];
    for (int i = tid; i < 64 * 24; i += 256) sm[OFF_XS + i] = x[cta_b0 * 24 + i];
    __syncthreads();

    const float thr1 = thr1p[0], thr2 = thr2p[0];

    // hoisted per-thread constants (this lane's neuron pair, per gate)
    float cb1r[4][2], cb2r[4][2], wi1r[4][2];
#pragma unroll
    for (int g = 0; g < 4; ++g)
#pragma unroll
        for (int n = 0; n < 2; ++n) {
            cb1r[g][n] = sm[OFF_CB1 + g * 64 + n0 + n];
            cb2r[g][n] = sm[OFF_CB2 + g * 64 + n0 + n];
            wi1r[g][n] = sm[OFF_WIH1 + g * 64 + n0 + n];
        }

    // register-resident state: [neuron 0/1][batch j]
    float syn1[2][8], mem1[2][8], syn2[2][8], mem2[2][8], spk1[2][8];
#pragma unroll
    for (int n = 0; n < 2; ++n)
#pragma unroll
        for (int j = 0; j < 8; ++j)
            syn1[n][j] = mem1[n][j] = syn2[n][j] = mem2[n][j] = spk1[n][j] = 0.0f;

    float oa[8][2];
#pragma unroll
    for (int j = 0; j < 8; ++j) oa[j][0] = oa[j][1] = 0.0f;

    unsigned long long acc[4][8];

#pragma unroll 1
    for (int t = 0; t < 25; ++t) {
        if (t < 24) {
            // ---- layer 1: gates = mem1 @ Whh1^T + x*Wih1 + b ----
#pragma unroll
            for (int g = 0; g < 4; ++g)
#pragma unroll
                for (int j = 0; j < 8; ++j) acc[g][j] = 0ull;
            gemm64(acc, sm + OFF_W1T, mem1, n0);
            float xv[8];
#pragma unroll
            for (int j = 0; j < 8; ++j) xv[j] = sm[OFF_XS + (bl + j) * 24 + t];
#pragma unroll
            for (int j = 0; j < 8; ++j) {
                float2 gi = unpack2(acc[0][j]);
                float2 gf = unpack2(acc[1][j]);
                float2 gg = unpack2(acc[2][j]);
                float2 go = unpack2(acc[3][j]);
#pragma unroll
                for (int n = 0; n < 2; ++n) {
                    float Gi = (n ? gi.y : gi.x) + cb1r[0][n] + xv[j] * wi1r[0][n];
                    float Gf = (n ? gf.y : gf.x) + cb1r[1][n] + xv[j] * wi1r[1][n];
                    float Gg = (n ? gg.y : gg.x) + cb1r[2][n] + xv[j] * wi1r[2][n];
                    float Go = (n ? go.y : go.x) + cb1r[3][n] + xv[j] * wi1r[3][n];
                    float sn  = sigf(Gf) * syn1[n][j] + sigf(Gi) * tanhf_fast(Gg);
                    float rst = (mem1[n][j] > thr1) ? thr1 : 0.0f;
                    float mn  = sigf(Go) * tanhf_fast(sn) - rst;
                    syn1[n][j] = sn;
                    mem1[n][j] = mn;
                    spk1[n][j] = (mn > thr1) ? 1.0f : 0.0f;
                }
            }
        }
        // ---- layer 2: input = spk1 (t<24) or mem1 (extra step t==24) ----
#pragma unroll
        for (int g = 0; g < 4; ++g)
#pragma unroll
            for (int j = 0; j < 8; ++j) acc[g][j] = 0ull;
        if (t < 24) gemm64(acc, sm + OFF_W2T, spk1, n0);
        else        gemm64(acc, sm + OFF_W2T, mem1, n0);
        gemm64(acc, sm + OFF_W2T + 64 * WSTRIDE, mem2, n0);

        const int wcol = t * 64;
        const float wo00 = sm[OFF_WOUT + wcol + n0];
        const float wo01 = sm[OFF_WOUT + wcol + n0 + 1];
        const float wo10 = sm[OFF_WOUT + 1664 + wcol + n0];
        const float wo11 = sm[OFF_WOUT + 1664 + wcol + n0 + 1];
#pragma unroll
        for (int j = 0; j < 8; ++j) {
            float2 gi = unpack2(acc[0][j]);
            float2 gf = unpack2(acc[1][j]);
            float2 gg = unpack2(acc[2][j]);
            float2 go = unpack2(acc[3][j]);
#pragma unroll
            for (int n = 0; n < 2; ++n) {
                float Gi = (n ? gi.y : gi.x) + cb2r[0][n];
                float Gf = (n ? gf.y : gf.x) + cb2r[1][n];
                float Gg = (n ? gg.y : gg.x) + cb2r[2][n];
                float Go = (n ? go.y : go.x) + cb2r[3][n];
                float sn  = sigf(Gf) * syn2[n][j] + sigf(Gi) * tanhf_fast(Gg);
                float rst = (mem2[n][j] > thr2) ? thr2 : 0.0f;
                float mn  = sigf(Go) * tanhf_fast(sn) - rst;
                syn2[n][j] = sn;
                mem2[n][j] = mn;
                float sp = (mn > thr2) ? 1.0f : 0.0f;
                oa[j][0] += sp * (n ? wo01 : wo00);
                oa[j][1] += sp * (n ? wo11 : wo10);
            }
        }
    }

    // ---- final mem2 contribution (columns 25*64 .. 25*64+63) ----
#pragma unroll
    for (int n = 0; n < 2; ++n) {
        float wm0 = sm[OFF_WOUT + 25 * 64 + n0 + n];
        float wm1 = sm[OFF_WOUT + 1664 + 25 * 64 + n0 + n];
#pragma unroll
        for (int j = 0; j < 8; ++j) {
            oa[j][0] += mem2[n][j] * wm0;
            oa[j][1] += mem2[n][j] * wm1;
        }
    }

    // ---- warp reduction over the 32 neuron-owner lanes ----
#pragma unroll
    for (int j = 0; j < 8; ++j)
#pragma unroll
        for (int k = 0; k < 2; ++k) {
            float v = oa[j][k];
#pragma unroll
            for (int off = 16; off; off >>= 1)
                v += __shfl_xor_sync(FULLMASK, v, off);
            oa[j][k] = v;
        }

    if (lane < 16) {
        int j = lane >> 1, k = lane & 1;
        out[(cta_b0 + bl + j) * 2 + k] = oa[j][k] + bout[k];
    }
}

extern "C" void kernel_launch(void* const* d_in, const int* in_sizes, int n_in,
                              void* d_out, int out_size) {
    const float* x    = (const float*)d_in[0];
    const float* Wih1 = (const float*)d_in[1];
    const float* Whh1 = (const float*)d_in[2];
    const float* bih1 = (const float*)d_in[3];
    const float* bhh1 = (const float*)d_in[4];
    const float* thr1 = (const float*)d_in[5];
    const float* Wih2 = (const float*)d_in[6];
    const float* Whh2 = (const float*)d_in[7];
    const float* bih2 = (const float*)d_in[8];
    const float* bhh2 = (const float*)d_in[9];
    const float* thr2 = (const float*)d_in[10];
    const float* Wout = (const float*)d_in[11];
    const float* bout = (const float*)d_in[12];
    float* out = (float*)d_out;

    int B = in_sizes[0] / 24;  // 65536

    // Unconditional, deterministic, graph-capture-legal (no static guards).
    cudaFuncSetAttribute(snn_kernel,
                         cudaFuncAttributeMaxDynamicSharedMemorySize,
                         SMEM_BYTES);

    snn_kernel<<<B / 64, 256, SMEM_BYTES>>>(
        x, Wih1, Whh1, bih1, bhh1, thr1,
        Wih2, Whh2, bih2, bhh2, thr2, Wout, bout, out);
}